// round 1
// baseline (speedup 1.0000x reference)
#include <cuda_runtime.h>
#include <cstdint>

#define NT 50000   // timesteps
#define ND 768     // lstm input dim
#define NF 128     // hidden (lstm2) = n_feats
#define NG 512     // 4*NF

// Scratch (allocation-free rule: __device__ globals)
__device__ float g_pre2[NT * NG];   // 102.4 MB: x @ Wih2^T + (bih2+bhh2)
__device__ float g_hs2 [NT * NF];   // 25.6 MB: lstm2 hidden states
__device__ float g_WfcT[NF * NF];   // transposed FC weight

__device__ __forceinline__ uint32_t s2u(const void* p) {
    uint32_t a;
    asm("{ .reg .u64 t; cvta.to.shared.u64 t, %1; cvt.u32.u64 %0, t; }"
        : "=r"(a) : "l"(p));
    return a;
}

__device__ __forceinline__ float sigf(float x) {
    // 1/(1+e^-x) via MUFU; rel err ~1e-6, saturates correctly at +-inf
    return __fdividef(1.f, 1.f + __expf(-x));
}
__device__ __forceinline__ float tanhfast(float x) {
    return fmaf(2.f, sigf(2.f * x), -1.f);
}

// ---------------- Wfc transpose (tiny, one-time) ----------------
__global__ void fc_transpose_kernel(const float* __restrict__ Wfc) {
    int idx = blockIdx.x * 256 + threadIdx.x;     // 16384 elems
    int j = idx >> 7, k = idx & 127;
    g_WfcT[k * NF + j] = Wfc[j * NF + k];
}

// ---------------- pre2 = x @ Wih2^T + bias   (50000x768x512 fp32 GEMM) ----------------
__global__ void __launch_bounds__(256) pre2_gemm_kernel(
    const float* __restrict__ x, const float* __restrict__ W,
    const float* __restrict__ b1, const float* __restrict__ b2) {
    __shared__ float As[16][68];   // 68*4B = 272B = 17*16B -> float4-aligned rows
    __shared__ float Bs[16][68];
    const int bm = blockIdx.x * 64;
    const int bn = blockIdx.y * 64;
    const int tid = threadIdx.x;
    const int tx = tid & 15, ty = tid >> 4;
    const int lr = tid >> 2, lq = tid & 3;

    float acc[4][4];
#pragma unroll
    for (int i = 0; i < 4; i++)
#pragma unroll
        for (int j = 0; j < 4; j++) acc[i][j] = 0.f;

    const int arow = bm + lr;
    const float* aptr = x + (size_t)arow * ND + lq * 4;
    const float* bptr = W + (size_t)(bn + lr) * ND + lq * 4;

    for (int k0 = 0; k0 < ND; k0 += 16) {
        float4 av = make_float4(0.f, 0.f, 0.f, 0.f);
        if (arow < NT) av = *(const float4*)(aptr + k0);
        float4 bv = *(const float4*)(bptr + k0);
        As[lq*4+0][lr] = av.x; As[lq*4+1][lr] = av.y;
        As[lq*4+2][lr] = av.z; As[lq*4+3][lr] = av.w;
        Bs[lq*4+0][lr] = bv.x; Bs[lq*4+1][lr] = bv.y;
        Bs[lq*4+2][lr] = bv.z; Bs[lq*4+3][lr] = bv.w;
        __syncthreads();
#pragma unroll
        for (int k = 0; k < 16; k++) {
            float4 a = *(const float4*)&As[k][ty * 4];
            float4 b = *(const float4*)&Bs[k][tx * 4];
            float a4[4] = {a.x, a.y, a.z, a.w};
            float b4[4] = {b.x, b.y, b.z, b.w};
#pragma unroll
            for (int i = 0; i < 4; i++)
#pragma unroll
                for (int j = 0; j < 4; j++)
                    acc[i][j] = fmaf(a4[i], b4[j], acc[i][j]);
        }
        __syncthreads();
    }
    float bb[4];
#pragma unroll
    for (int j = 0; j < 4; j++) bb[j] = b1[bn + tx*4 + j] + b2[bn + tx*4 + j];
#pragma unroll
    for (int i = 0; i < 4; i++) {
        int row = bm + ty * 4 + i;
        if (row < NT) {
#pragma unroll
            for (int j = 0; j < 4; j++)
                g_pre2[(size_t)row * NG + bn + tx * 4 + j] = acc[i][j] + bb[j];
        }
    }
}

// ---------------- sequential LSTM scan: 2-CTA cluster, weights in registers ----------------
// CTA r owns output elements j in [r*64, r*64+64): 256 rows of Whh2.
// 512 threads: thread = (row_local in [0,256)) x (seg in {0,1}); each holds 64 fp32
// weights packed as 32 u64 (f32x2). h exchanged per step via DSMEM + mbarrier (128 arrivals).
__global__ void __cluster_dims__(2, 1, 1) __launch_bounds__(512, 1)
scan_kernel(const float* __restrict__ Whh, const float* __restrict__ h0,
            const float* __restrict__ c0) {
    __shared__ alignas(16) float h_s[2][NF];   // double-buffered full h
    __shared__ float gates_s[256];
    __shared__ alignas(8) unsigned long long mbar;

    const unsigned tid = threadIdx.x;
    unsigned rank;
    asm("mov.u32 %0, %%cluster_ctarank;" : "=r"(rank));
    const unsigned peer = rank ^ 1u;
    const unsigned lane = tid & 31u, warp = tid >> 5;
    const unsigned seg = lane & 1u;                      // column half: 0 -> h[0:64), 1 -> h[64:128)
    const unsigned row_local = warp * 16u + (lane >> 1); // 0..255
    const unsigned gate = row_local >> 6;                // 0:i 1:f 2:g 3:o
    const unsigned jloc = row_local & 63u;
    const unsigned grow = gate * NF + rank * 64u + jloc; // global Whh2 row

    // --- weights into registers, pre-packed for fma.rn.f32x2 ---
    unsigned long long wp[32];
    {
        const ulonglong2* wv =
            reinterpret_cast<const ulonglong2*>(Whh + (size_t)grow * NF + seg * 64u);
#pragma unroll
        for (int i = 0; i < 16; i++) {
            ulonglong2 v = wv[i];
            wp[2 * i]     = v.x;
            wp[2 * i + 1] = v.y;
        }
    }

    // --- init state ---
    if (tid < NF) h_s[0][tid] = h0[tid];
    const unsigned gj = rank * 64u + (tid & 63u);
    float c = 0.f;
    if (tid < 64u) c = c0[gj];
    if (tid == 0u) {
        asm volatile("mbarrier.init.shared.b64 [%0], %1;"
                     :: "r"(s2u(&mbar)), "r"(128u) : "memory");
    }
    __syncthreads();
    // all mbarriers + initial h visible cluster-wide before any remote arrive
    asm volatile("barrier.cluster.arrive.aligned;" ::: "memory");
    asm volatile("barrier.cluster.wait.aligned;"   ::: "memory");

    const uint32_t mbar_l = s2u(&mbar);
    uint32_t mbar_r;
    asm("mapa.shared::cluster.u32 %0, %1, %2;" : "=r"(mbar_r) : "r"(mbar_l), "r"(peer));
    const uint32_t hbase = s2u(&h_s[0][0]);
    uint32_t hr[2];
    {
        uint32_t l0 = hbase + gj * 4u;
        uint32_t l1 = hbase + (NF + gj) * 4u;
        asm("mapa.shared::cluster.u32 %0, %1, %2;" : "=r"(hr[0]) : "r"(l0), "r"(peer));
        asm("mapa.shared::cluster.u32 %0, %1, %2;" : "=r"(hr[1]) : "r"(l1), "r"(peer));
    }

    float pre_cur = 0.f;
    if (seg == 0u) pre_cur = g_pre2[grow];   // t = 0

    unsigned buf = 0u;
#pragma unroll 1
    for (int t = 0; t < NT; t++) {
        // prefetch next step's pre-activation (hides L2/DRAM latency under the dot)
        float pre_next = 0.f;
        if (seg == 0u && t + 1 < NT)
            pre_next = g_pre2[(size_t)(t + 1) * NG + grow];

        // --- 64-wide dot: registers (weights) x smem-broadcast (h), packed f32x2 ---
        unsigned long long a0 = 0ull, a1 = 0ull;
        const ulonglong2* hp =
            reinterpret_cast<const ulonglong2*>(&h_s[buf][seg * 64u]);
#pragma unroll
        for (int i = 0; i < 16; i++) {
            ulonglong2 hv = hp[i];
            asm("fma.rn.f32x2 %0, %1, %2, %0;" : "+l"(a0) : "l"(wp[2*i]),     "l"(hv.x));
            asm("fma.rn.f32x2 %0, %1, %2, %0;" : "+l"(a1) : "l"(wp[2*i + 1]), "l"(hv.y));
        }
        float s0lo, s0hi, s1lo, s1hi;
        asm("mov.b64 {%0, %1}, %2;" : "=f"(s0lo), "=f"(s0hi) : "l"(a0));
        asm("mov.b64 {%0, %1}, %2;" : "=f"(s1lo), "=f"(s1hi) : "l"(a1));
        float acc = (s0lo + s0hi) + (s1lo + s1hi);
        acc += __shfl_xor_sync(0xffffffffu, acc, 1);     // combine the two column halves
        if (seg == 0u) gates_s[row_local] = acc + pre_cur;
        __syncthreads();

        // --- cell update (64 threads), publish h locally + to peer CTA ---
        if (tid < 64u) {
            float gi = gates_s[tid];
            float gf = gates_s[64u + tid];
            float gg = gates_s[128u + tid];
            float go = gates_s[192u + tid];
            float ig = sigf(gi);
            float fg = sigf(gf);
            float cg = tanhfast(gg);
            float og = sigf(go);
            c = fmaf(fg, c, ig * cg);
            float hn = og * tanhfast(c);
            h_s[buf ^ 1u][gj] = hn;
            asm volatile("st.shared::cluster.f32 [%0], %1;"
                         :: "r"(hr[buf ^ 1u]), "f"(hn) : "memory");
            g_hs2[(size_t)t * NF + gj] = hn;
            asm volatile("mbarrier.arrive.shared.b64 _, [%0];"
                         :: "r"(mbar_l) : "memory");
            asm volatile("mbarrier.arrive.release.cluster.shared::cluster.b64 _, [%0];"
                         :: "r"(mbar_r) : "memory");
        }
        // all 512 threads wait for 64 local + 64 remote h writes (parity = t & 1)
        {
            unsigned par = (unsigned)t & 1u;
            asm volatile(
                "{\n\t"
                ".reg .pred P;\n\t"
                "W_%=:\n\t"
                "mbarrier.try_wait.parity.acquire.cluster.shared::cta.b64 P, [%0], %1, 0x989680;\n\t"
                "@!P bra W_%=;\n\t"
                "}"
                :: "r"(mbar_l), "r"(par) : "memory");
        }
        pre_cur = pre_next;
        buf ^= 1u;
    }
}

// ---------------- out = sigmoid(hs2 @ Wfc^T + bfc) ----------------
__global__ void __launch_bounds__(128) out_kernel(const float* __restrict__ bfc,
                                                  float* __restrict__ out) {
    __shared__ float hrow[NF];
    const int t = blockIdx.x;
    const int j = threadIdx.x;
    hrow[j] = g_hs2[(size_t)t * NF + j];
    __syncthreads();
    float acc = bfc[j];
    const float* w = g_WfcT + j;   // column j, coalesced across threads, L1/L2 resident
#pragma unroll 16
    for (int k = 0; k < NF; k++) acc = fmaf(hrow[k], w[(size_t)k * NF], acc);
    out[(size_t)t * NF + j] = sigf(acc);
}

extern "C" void kernel_launch(void* const* d_in, const int* in_sizes, int n_in,
                              void* d_out, int out_size) {
    (void)in_sizes; (void)n_in; (void)out_size;
    const float* x    = (const float*)d_in[0];
    const float* h2   = (const float*)d_in[3];
    const float* c2   = (const float*)d_in[4];
    const float* Wih2 = (const float*)d_in[9];
    const float* Whh2 = (const float*)d_in[10];
    const float* bih2 = (const float*)d_in[11];
    const float* bhh2 = (const float*)d_in[12];
    const float* Wfc  = (const float*)d_in[13];
    const float* bfc  = (const float*)d_in[14];
    float* out = (float*)d_out;

    // lstm1 (inputs 1,2,5..8) is dead code in the reference: its output is discarded.
    fc_transpose_kernel<<<64, 256>>>(Wfc);
    dim3 g1((NT + 63) / 64, NG / 64);
    pre2_gemm_kernel<<<g1, 256>>>(x, Wih2, bih2, bhh2);
    scan_kernel<<<2, 512>>>(Whh2, h2, c2);
    out_kernel<<<NT, 128>>>(bfc, out);
}

// round 8
// speedup vs baseline: 1.1276x; 1.1276x over previous
#include <cuda_runtime.h>
#include <cstdint>

#define NT 50000   // timesteps
#define ND 768     // lstm input dim
#define NF 128     // hidden (lstm2) = n_feats
#define NG 512     // 4*NF

// Scratch (allocation-free rule: __device__ globals)
__device__ float g_pre2[NT * NG];   // 102.4 MB: x @ Wih2^T + (bih2+bhh2)
__device__ float g_hs2 [NT * NF];   // 25.6 MB: lstm2 hidden states
__device__ float g_WfcT[NF * NF];   // transposed FC weight

__device__ __forceinline__ uint32_t s2u(const void* p) {
    uint32_t a;
    asm("{ .reg .u64 t; cvta.to.shared.u64 t, %1; cvt.u32.u64 %0, t; }"
        : "=r"(a) : "l"(p));
    return a;
}

__device__ __forceinline__ float sigf(float x) {
    return __fdividef(1.f, 1.f + __expf(-x));
}
__device__ __forceinline__ float tanhfast(float x) {
    return fmaf(2.f, sigf(2.f * x), -1.f);
}

// ---------------- Wfc transpose (tiny, one-time) ----------------
__global__ void fc_transpose_kernel(const float* __restrict__ Wfc) {
    int idx = blockIdx.x * 256 + threadIdx.x;     // 16384 elems
    int j = idx >> 7, k = idx & 127;
    g_WfcT[k * NF + j] = Wfc[j * NF + k];
}

// ---------------- pre2 = x @ Wih2^T + bias   (50000x768x512 fp32 GEMM) ----------------
__global__ void __launch_bounds__(256) pre2_gemm_kernel(
    const float* __restrict__ x, const float* __restrict__ W,
    const float* __restrict__ b1, const float* __restrict__ b2) {
    __shared__ float As[16][68];
    __shared__ float Bs[16][68];
    const int bm = blockIdx.x * 64;
    const int bn = blockIdx.y * 64;
    const int tid = threadIdx.x;
    const int tx = tid & 15, ty = tid >> 4;
    const int lr = tid >> 2, lq = tid & 3;

    float acc[4][4];
#pragma unroll
    for (int i = 0; i < 4; i++)
#pragma unroll
        for (int j = 0; j < 4; j++) acc[i][j] = 0.f;

    const int arow = bm + lr;
    const float* aptr = x + (size_t)arow * ND + lq * 4;
    const float* bptr = W + (size_t)(bn + lr) * ND + lq * 4;

    for (int k0 = 0; k0 < ND; k0 += 16) {
        float4 av = make_float4(0.f, 0.f, 0.f, 0.f);
        if (arow < NT) av = *(const float4*)(aptr + k0);
        float4 bv = *(const float4*)(bptr + k0);
        As[lq*4+0][lr] = av.x; As[lq*4+1][lr] = av.y;
        As[lq*4+2][lr] = av.z; As[lq*4+3][lr] = av.w;
        Bs[lq*4+0][lr] = bv.x; Bs[lq*4+1][lr] = bv.y;
        Bs[lq*4+2][lr] = bv.z; Bs[lq*4+3][lr] = bv.w;
        __syncthreads();
#pragma unroll
        for (int k = 0; k < 16; k++) {
            float4 a = *(const float4*)&As[k][ty * 4];
            float4 b = *(const float4*)&Bs[k][tx * 4];
            float a4[4] = {a.x, a.y, a.z, a.w};
            float b4[4] = {b.x, b.y, b.z, b.w};
#pragma unroll
            for (int i = 0; i < 4; i++)
#pragma unroll
                for (int j = 0; j < 4; j++)
                    acc[i][j] = fmaf(a4[i], b4[j], acc[i][j]);
        }
        __syncthreads();
    }
    float bb[4];
#pragma unroll
    for (int j = 0; j < 4; j++) bb[j] = b1[bn + tx*4 + j] + b2[bn + tx*4 + j];
#pragma unroll
    for (int i = 0; i < 4; i++) {
        int row = bm + ty * 4 + i;
        if (row < NT) {
#pragma unroll
            for (int j = 0; j < 4; j++)
                g_pre2[(size_t)row * NG + bn + tx * 4 + j] = acc[i][j] + bb[j];
        }
    }
}

// ---------------- sequential LSTM scan: 2-CTA cluster, partial-shipping ----------------
// Each CTA holds ALL 512 gate-rows of Whh2, but only its OWN 64-column half, in
// registers (512 rows x 64 cols x 4B = 128KB). Per step each thread computes one
// row's partial dot over the local h half (no remote h needed). Warps 8..15
// compute partials for the PEER's rows and ship them (256x st.shared::cluster +
// ONE release-arrive on the peer's count-1 mbarrier). Warps 0..7 keep their own
// partials in registers, wait on the single-arrival mbarrier, add recv + pre,
// apply activations in-lane (parallel MUFU), gather via shfl, update c/h.
__global__ void __cluster_dims__(2, 1, 1) __launch_bounds__(512, 1)
scan_kernel(const float* __restrict__ Whh, const float* __restrict__ h0,
            const float* __restrict__ c0) {
    __shared__ alignas(16) float h_s[2][64];    // my CTA's h half, double-buffered
    __shared__ alignas(16) float p_s[2][256];   // received partials, double-buffered
    __shared__ alignas(8) unsigned long long mbar;

    const unsigned tid = threadIdx.x;
    unsigned rank;
    asm("mov.u32 %0, %%cluster_ctarank;" : "=r"(rank));
    const unsigned peer = rank ^ 1u;
    const unsigned half = tid >> 8;             // 0: my rows, 1: peer's rows
    const unsigned w8   = (tid >> 5) & 7u;      // warp within half
    const unsigned l    = tid & 31u;
    const unsigned jw   = l >> 2;               // output within warp (0..7)
    const unsigned gate = l & 3u;               // 0:i 1:f 2:g 3:o
    const unsigned jl   = w8 * 8u + jw;         // output within owner CTA (0..63)
    const unsigned owner = half ? peer : rank;
    const unsigned grow = gate * NF + owner * 64u + jl;  // global Whh2 row
    const unsigned pidx = gate * 64u + jl;               // partial slot

    // --- weights into registers: my column half of row `grow`, packed f32x2 ---
    unsigned long long wp[32];
    {
        const ulonglong2* wv =
            reinterpret_cast<const ulonglong2*>(Whh + (size_t)grow * NF + rank * 64u);
#pragma unroll
        for (int i = 0; i < 16; i++) {
            ulonglong2 v = wv[i];
            wp[2 * i]     = v.x;
            wp[2 * i + 1] = v.y;
        }
    }

    // --- init state ---
    if (tid < 64u) h_s[0][tid] = h0[rank * 64u + tid];
    float c = 0.f, pre_cur = 0.f;
    if (half == 0u) {
        pre_cur = g_pre2[grow];                 // t = 0
        if (gate == 0u) c = c0[rank * 64u + jl];
    }
    if (tid == 0u) {
        asm volatile("mbarrier.init.shared.b64 [%0], %1;"
                     :: "r"(s2u(&mbar)), "r"(1u) : "memory");
    }
    __syncthreads();
    asm volatile("barrier.cluster.arrive.aligned;" ::: "memory");
    asm volatile("barrier.cluster.wait.aligned;"   ::: "memory");

    const uint32_t mbar_l = s2u(&mbar);
    uint32_t mbar_r;
    asm("mapa.shared::cluster.u32 %0, %1, %2;" : "=r"(mbar_r) : "r"(mbar_l), "r"(peer));
    uint32_t ps_r[2];
    {
        uint32_t l0 = s2u(&p_s[0][pidx]);
        uint32_t l1 = s2u(&p_s[1][pidx]);
        asm("mapa.shared::cluster.u32 %0, %1, %2;" : "=r"(ps_r[0]) : "r"(l0), "r"(peer));
        asm("mapa.shared::cluster.u32 %0, %1, %2;" : "=r"(ps_r[1]) : "r"(l1), "r"(peer));
    }

#pragma unroll 1
    for (int t = 0; t < NT; t++) {
        const unsigned buf = (unsigned)t & 1u;

        // --- partial dot over my local 64-column h half (smem broadcast) ---
        unsigned long long a0 = 0ull, a1 = 0ull, a2 = 0ull, a3 = 0ull;
        const ulonglong2* hp = reinterpret_cast<const ulonglong2*>(&h_s[buf][0]);
#pragma unroll
        for (int i = 0; i < 8; i++) {
            ulonglong2 hv0 = hp[2 * i];
            ulonglong2 hv1 = hp[2 * i + 1];
            asm("fma.rn.f32x2 %0, %1, %2, %0;" : "+l"(a0) : "l"(wp[4*i+0]), "l"(hv0.x));
            asm("fma.rn.f32x2 %0, %1, %2, %0;" : "+l"(a1) : "l"(wp[4*i+1]), "l"(hv0.y));
            asm("fma.rn.f32x2 %0, %1, %2, %0;" : "+l"(a2) : "l"(wp[4*i+2]), "l"(hv1.x));
            asm("fma.rn.f32x2 %0, %1, %2, %0;" : "+l"(a3) : "l"(wp[4*i+3]), "l"(hv1.y));
        }
        asm("add.rn.f32x2 %0, %0, %1;" : "+l"(a0) : "l"(a1));
        asm("add.rn.f32x2 %0, %0, %1;" : "+l"(a2) : "l"(a3));
        asm("add.rn.f32x2 %0, %0, %1;" : "+l"(a0) : "l"(a2));
        float plo, phi;
        asm("mov.b64 {%0, %1}, %2;" : "=f"(plo), "=f"(phi) : "l"(a0));
        float part = plo + phi;

        if (half) {
            // --- ship partial for peer's row; one aggregated release-arrive ---
            asm volatile("st.shared::cluster.f32 [%0], %1;"
                         :: "r"(ps_r[buf]), "f"(part) : "memory");
            asm volatile("bar.sync 1, 256;" ::: "memory");
            if (tid == 256u) {
                asm volatile("mbarrier.arrive.release.cluster.shared::cluster.b64 _, [%0];"
                             :: "r"(mbar_r) : "memory");
            }
        } else {
            // prefetch next pre-activation during the wait
            float pre_next = 0.f;
            if (t + 1 < NT) pre_next = g_pre2[(size_t)(t + 1) * NG + grow];

            // wait for peer's partials of step t (single arrival, parity = t&1)
            asm volatile(
                "{\n\t"
                ".reg .pred P;\n\t"
                "W_%=:\n\t"
                "mbarrier.try_wait.parity.acquire.cluster.shared::cta.b64 P, [%0], %1, 0x989680;\n\t"
                "@!P bra W_%=;\n\t"
                "}"
                :: "r"(mbar_l), "r"(buf) : "memory");

            float g = part + pre_cur + p_s[buf][pidx];
            // in-lane activation: sigmoid for i/f/o lanes, tanh for g lane (parallel MUFU)
            float act = (gate == 2u) ? tanhfast(g) : sigf(g);
            unsigned lb = l & ~3u;
            float fg = __shfl_sync(0xffffffffu, act, lb + 1u);
            float cg = __shfl_sync(0xffffffffu, act, lb + 2u);
            float og = __shfl_sync(0xffffffffu, act, lb + 3u);
            if (gate == 0u) {
                c = fmaf(fg, c, act * cg);      // act == i-gate here
                float hn = og * tanhfast(c);
                h_s[buf ^ 1u][jl] = hn;
                g_hs2[(size_t)t * NF + rank * 64u + jl] = hn;
            }
            pre_cur = pre_next;
        }
        __syncthreads();
    }

    // no CTA may exit while the peer might still store into its smem
    asm volatile("barrier.cluster.arrive.aligned;" ::: "memory");
    asm volatile("barrier.cluster.wait.aligned;"   ::: "memory");
}

// ---------------- out = sigmoid(hs2 @ Wfc^T + bfc) ----------------
__global__ void __launch_bounds__(128) out_kernel(const float* __restrict__ bfc,
                                                  float* __restrict__ out) {
    __shared__ float hrow[NF];
    const int t = blockIdx.x;
    const int j = threadIdx.x;
    hrow[j] = g_hs2[(size_t)t * NF + j];
    __syncthreads();
    float acc = bfc[j];
    const float* w = g_WfcT + j;
#pragma unroll 16
    for (int k = 0; k < NF; k++) acc = fmaf(hrow[k], w[(size_t)k * NF], acc);
    out[(size_t)t * NF + j] = sigf(acc);
}

extern "C" void kernel_launch(void* const* d_in, const int* in_sizes, int n_in,
                              void* d_out, int out_size) {
    (void)in_sizes; (void)n_in; (void)out_size;
    const float* x    = (const float*)d_in[0];
    const float* h2   = (const float*)d_in[3];
    const float* c2   = (const float*)d_in[4];
    const float* Wih2 = (const float*)d_in[9];
    const float* Whh2 = (const float*)d_in[10];
    const float* bih2 = (const float*)d_in[11];
    const float* bhh2 = (const float*)d_in[12];
    const float* Wfc  = (const float*)d_in[13];
    const float* bfc  = (const float*)d_in[14];
    float* out = (float*)d_out;

    // lstm1 (inputs 1,2,5..8) is dead code in the reference: its output is discarded.
    fc_transpose_kernel<<<64, 256>>>(Wfc);
    dim3 g1((NT + 63) / 64, NG / 64);
    pre2_gemm_kernel<<<g1, 256>>>(x, Wih2, bih2, bhh2);
    scan_kernel<<<2, 512>>>(Whh2, h2, c2);
    out_kernel<<<NT, 128>>>(bfc, out);
}